// round 9
// baseline (speedup 1.0000x reference)
#include <cuda_runtime.h>
#include <cuda_bf16.h>
#include <cstdint>

// Fused: y = AdaptiveAvgPool2d(56)( ReLU(x * std + mean) ), separable 2-pass,
// 2 planes per CTA with software pipelining (prefetch plane1's LDGs before
// plane0's store phase so reads stay in flight during the write burst).
//
// Phase A: 4 threads per input row; each loads S/4 cols from GMEM, applies
//   affine+ReLU, column-pools to 14 outputs with COMPILE-TIME bins
//   (quarter boundaries exact: col(14q)=qS/4), writes T[S][56] (stride 60).
// Phase B: out row i = T[r0] (cnt==1, majority) or 0.5*(T[r0]+T[r0+1]);
//   second LDS.128 only when the bin spans 2 rows. STG.128.cs streaming.

#define TROW 60
#define TPB  196

__device__ __forceinline__ void stcs4(float* p, float4 v) {
    asm volatile("st.global.cs.v4.f32 [%0], {%1,%2,%3,%4};"
                 :: "l"(p), "f"(v.x), "f"(v.y), "f"(v.z), "f"(v.w) : "memory");
}

// Load this thread's quarter-row of the plane into registers (no consume).
template<int S>
__device__ __forceinline__
void load_q(const float* __restrict__ plane, int t, float* __restrict__ x)
{
    constexpr int NC = S / 4;
    const int r = t >> 2;
    const int q = t & 3;
    const float* rp = plane + r * S + q * NC;
    if constexpr (NC % 4 == 0) {
        #pragma unroll
        for (int k = 0; k < NC / 4; k++) {
            float4 v = ((const float4*)rp)[k];
            x[4*k+0] = v.x; x[4*k+1] = v.y; x[4*k+2] = v.z; x[4*k+3] = v.w;
        }
    } else {
        #pragma unroll
        for (int k = 0; k < NC / 2; k++) {
            float2 v = ((const float2*)rp)[k];
            x[2*k] = v.x; x[2*k+1] = v.y;
        }
    }
}

// affine+ReLU the registers, column-pool to 14 outputs, write T segment.
template<int S>
__device__ __forceinline__
void pool_to_T(float* __restrict__ x, float mean, float sd,
               float* __restrict__ T, int t)
{
    constexpr int NC = S / 4;
    const int r = t >> 2;
    const int q = t & 3;
    float y[NC];
    #pragma unroll
    for (int k = 0; k < NC; k++)
        y[k] = fmaxf(fmaf(x[k], sd, mean), 0.0f);

    float* Trow = &T[r * TROW + q * 14];
    #pragma unroll
    for (int jl = 0; jl < 14; jl += 2) {
        float2 v;
        {
            const int c0  = (jl * S) / 56;
            const int cnt = ((jl + 1) * S + 55) / 56 - c0;
            v.x = (cnt == 1) ? y[c0] : 0.5f * (y[c0] + y[c0 + 1]);
        }
        {
            const int c0  = ((jl + 1) * S) / 56;
            const int cnt = ((jl + 2) * S + 55) / 56 - c0;
            v.y = (cnt == 1) ? y[c0] : 0.5f * (y[c0] + y[c0 + 1]);
        }
        *(float2*)(Trow + jl) = v;
    }
}

// Row pool T -> output plane; conditional second row load; streaming stores.
template<int S>
__device__ __forceinline__
void phaseB(const float* __restrict__ T, float* __restrict__ outp, int t)
{
    #pragma unroll
    for (int l = 0; l < 4; l++) {
        const int qd = t + l * TPB;
        const int i  = qd / 14;
        const int j0 = (qd - i * 14) * 4;

        const int r0  = (i * S) / 56;
        const int cnt = ((i + 1) * S + 55) / 56 - r0;

        float4 res = *(const float4*)&T[r0 * TROW + j0];
        if (cnt == 2) {
            const float4 b = *(const float4*)&T[(r0 + 1) * TROW + j0];
            res.x = 0.5f * (res.x + b.x);
            res.y = 0.5f * (res.y + b.y);
            res.z = 0.5f * (res.z + b.z);
            res.w = 0.5f * (res.w + b.w);
        }
        stcs4(outp + i * 56 + j0, res);
    }
}

template<int S>
__device__ __forceinline__
void do_pair(const float* __restrict__ p0,   // plane bid0 (bid1 = bid0 + 1 is adjacent)
             float m0, float s0, float m1, float s1,
             float* __restrict__ out0, float* __restrict__ T, int t)
{
    constexpr int NC = S / 4;
    float x[NC];
    const bool act = (t < 4 * S);

    if (act) {
        load_q<S>(p0, t, x);
        pool_to_T<S>(x, m0, s0, T, t);
    }
    __syncthreads();

    if (act) load_q<S>(p0 + S * S, t, x);   // prefetch plane 1 (consumed after sync)
    phaseB<S>(T, out0, t);
    __syncthreads();

    if (act) pool_to_T<S>(x, m1, s1, T, t);
    __syncthreads();

    phaseB<S>(T, out0 + 3136, t);
}

__global__ __launch_bounds__(TPB, 8)
void ppin_fused_kernel(const float* __restrict__ p24,
                       const float* __restrict__ p32,
                       const float* __restrict__ p48,
                       const float* __restrict__ smean,
                       const float* __restrict__ sstd,
                       float* __restrict__ out)
{
    __shared__ float T[48 * TROW];

    // CTA handles planes bid0 = n*256 + 2k and bid0+1 (same patch, adjacent
    // channels -> same S, contiguous input & output). n = b%96 interleaves
    // the three S-groups within each wave.
    const int b   = blockIdx.x;
    const int n   = b % 96;
    const int k   = b / 96;            // 0..127
    const int bid = n * 256 + 2 * k;

    const int t = threadIdx.x;
    const float m0 = smean[bid],     s0 = sstd[bid];
    const float m1 = smean[bid + 1], s1 = sstd[bid + 1];
    float* out0 = out + (size_t)bid * 3136;

    if (n < 32) {
        do_pair<24>(p24 + (size_t)bid * (24 * 24), m0, s0, m1, s1, out0, T, t);
    } else if (n < 64) {
        do_pair<32>(p32 + (size_t)(bid - 32 * 256) * (32 * 32), m0, s0, m1, s1, out0, T, t);
    } else {
        do_pair<48>(p48 + (size_t)(bid - 64 * 256) * (48 * 48), m0, s0, m1, s1, out0, T, t);
    }
}

extern "C" void kernel_launch(void* const* d_in, const int* in_sizes, int n_in,
                              void* d_out, int out_size)
{
    const float* p24   = (const float*)d_in[0];
    const float* p32   = (const float*)d_in[1];
    const float* p48   = (const float*)d_in[2];
    const float* smean = (const float*)d_in[3];
    const float* sstd  = (const float*)d_in[4];
    float* out = (float*)d_out;

    ppin_fused_kernel<<<96 * 128, TPB>>>(p24, p32, p48, smean, sstd, out);
}

// round 10
// speedup vs baseline: 1.0476x; 1.0476x over previous
#include <cuda_runtime.h>
#include <cuda_bf16.h>
#include <cstdint>

// Fused: y = AdaptiveAvgPool2d(56)( ReLU(x * std + mean) ), separable 2-pass.
// Single launch; per-CTA uniform dispatch to templated body (S = 24/32/48).
//
// Phase A: 4 threads per input row; each loads S/4 cols from GMEM with
//   __ldcs (evict-first: planes are read exactly once -> keep L2 for the
//   write stream), applies affine+ReLU, column-pools to 14 outputs with
//   COMPILE-TIME bins (quarter boundaries exact: col(14q)=qS/4),
//   writes T[S][56] (stride 60 words, conflict-free).
// Phase B: out row i = T[r0] (cnt==1, majority) or 0.5*(T[r0]+T[r0+1]);
//   second LDS.128 only when the bin spans 2 rows. STG.128.cs streaming.
//
// bid remap (n = b % 96) interleaves the three S-groups within each wave to
// balance HBM read/write mix and per-CTA duration.

#define TROW 60   // T row stride in floats (240B, 16B-aligned, conflict-free)
#define TPB  196

__device__ __forceinline__ void stcs4(float* p, float4 v) {
    asm volatile("st.global.cs.v4.f32 [%0], {%1,%2,%3,%4};"
                 :: "l"(p), "f"(v.x), "f"(v.y), "f"(v.z), "f"(v.w) : "memory");
}

template<int S>
__device__ __forceinline__
void do_plane(const float* __restrict__ plane, float mean, float sd,
              float* __restrict__ outp, float* __restrict__ T, int t)
{
    constexpr int NC = S / 4;   // input cols per phase-A thread

    // ── Phase A: evict-first load + affine + ReLU + column pool ──
    if (t < 4 * S) {
        const int r = t >> 2;
        const int q = t & 3;
        const float* rp = plane + r * S + q * NC;

        float x[NC];
        if constexpr (NC % 4 == 0) {
            #pragma unroll
            for (int k = 0; k < NC / 4; k++) {
                float4 v = __ldcs((const float4*)rp + k);
                x[4*k+0] = v.x; x[4*k+1] = v.y; x[4*k+2] = v.z; x[4*k+3] = v.w;
            }
        } else {
            #pragma unroll
            for (int k = 0; k < NC / 2; k++) {
                float2 v = __ldcs((const float2*)rp + k);
                x[2*k] = v.x; x[2*k+1] = v.y;
            }
        }
        #pragma unroll
        for (int k = 0; k < NC; k++)
            x[k] = fmaxf(fmaf(x[k], sd, mean), 0.0f);

        float* Trow = &T[r * TROW + q * 14];
        #pragma unroll
        for (int jl = 0; jl < 14; jl += 2) {
            float2 v;
            {
                const int c0  = (jl * S) / 56;
                const int cnt = ((jl + 1) * S + 55) / 56 - c0;
                v.x = (cnt == 1) ? x[c0] : 0.5f * (x[c0] + x[c0 + 1]);
            }
            {
                const int c0  = ((jl + 1) * S) / 56;
                const int cnt = ((jl + 2) * S + 55) / 56 - c0;
                v.y = (cnt == 1) ? x[c0] : 0.5f * (x[c0] + x[c0 + 1]);
            }
            *(float2*)(Trow + jl) = v;
        }
    }
    __syncthreads();

    // ── Phase B: row pool; second row load only when the bin spans 2 rows ──
    #pragma unroll
    for (int l = 0; l < 4; l++) {
        const int qd = t + l * TPB;
        const int i  = qd / 14;
        const int j0 = (qd - i * 14) * 4;

        const int r0  = (i * S) / 56;
        const int cnt = ((i + 1) * S + 55) / 56 - r0;

        float4 res = *(const float4*)&T[r0 * TROW + j0];
        if (cnt == 2) {
            const float4 b = *(const float4*)&T[(r0 + 1) * TROW + j0];
            res.x = 0.5f * (res.x + b.x);
            res.y = 0.5f * (res.y + b.y);
            res.z = 0.5f * (res.z + b.z);
            res.w = 0.5f * (res.w + b.w);
        }
        stcs4(outp + i * 56 + j0, res);
    }
}

__global__ __launch_bounds__(TPB, 10)
void ppin_fused_kernel(const float* __restrict__ p24,
                       const float* __restrict__ p32,
                       const float* __restrict__ p48,
                       const float* __restrict__ smean,
                       const float* __restrict__ sstd,
                       float* __restrict__ out)
{
    __shared__ float T[48 * TROW];     // column-pooled intermediate

    // Interleave S-groups within each wave: consecutive blockIdx -> different n.
    const int b = blockIdx.x;
    const int n = b % 96;              // patch index (0..95)
    const int c = b / 96;              // channel (0..255)
    const int bid = n * 256 + c;       // plane index in reference layout

    const int t = threadIdx.x;
    const float mean = smean[bid];
    const float sd   = sstd[bid];
    float* outp = out + (size_t)bid * 3136;

    if (n < 32) {
        do_plane<24>(p24 + (size_t)bid * (24 * 24), mean, sd, outp, T, t);
    } else if (n < 64) {
        do_plane<32>(p32 + (size_t)(bid - 32 * 256) * (32 * 32), mean, sd, outp, T, t);
    } else {
        do_plane<48>(p48 + (size_t)(bid - 64 * 256) * (48 * 48), mean, sd, outp, T, t);
    }
}

extern "C" void kernel_launch(void* const* d_in, const int* in_sizes, int n_in,
                              void* d_out, int out_size)
{
    const float* p24   = (const float*)d_in[0];
    const float* p32   = (const float*)d_in[1];
    const float* p48   = (const float*)d_in[2];
    const float* smean = (const float*)d_in[3];
    const float* sstd  = (const float*)d_in[4];
    float* out = (float*)d_out;

    ppin_fused_kernel<<<96 * 256, TPB>>>(p24, p32, p48, smean, sstd, out);
}